// round 1
// baseline (speedup 1.0000x reference)
#include <cuda_runtime.h>
#include <cuda_bf16.h>
#include <cstdint>

#define HW   256
#define HW2  (HW * HW)
#define MAX_BS 128

// Scratch (no allocations allowed): per-cell winning source linear index, -1 = empty.
__device__ int g_scatter[MAX_BS * HW2];   // 33.5 MB
__device__ int g_empty[MAX_BS];

// ---------------------------------------------------------------------------
// K1: per-batch count of seg>0.5 -> empty flag (all-True fallback)
// ---------------------------------------------------------------------------
__global__ void count_kernel(const float* __restrict__ seg) {
    int b = blockIdx.x;
    const float4* s4 = reinterpret_cast<const float4*>(seg + (size_t)b * HW2);
    int cnt = 0;
    for (int i = threadIdx.x; i < HW2 / 4; i += blockDim.x) {
        float4 v = s4[i];
        cnt += (v.x > 0.5f) + (v.y > 0.5f) + (v.z > 0.5f) + (v.w > 0.5f);
    }
    #pragma unroll
    for (int o = 16; o; o >>= 1) cnt += __shfl_down_sync(0xffffffffu, cnt, o);
    __shared__ int sh[32];
    if ((threadIdx.x & 31) == 0) sh[threadIdx.x >> 5] = cnt;
    __syncthreads();
    if (threadIdx.x == 0) {
        int tot = 0;
        int nw = blockDim.x >> 5;
        for (int i = 0; i < nw; i++) tot += sh[i];
        g_empty[b] = (tot == 0) ? 1 : 0;
    }
}

// ---------------------------------------------------------------------------
// K2: scatter — last-writer-in-row-major-order wins == max source linear index
// ---------------------------------------------------------------------------
__global__ void scatter_kernel(const float* __restrict__ grid,
                               const float* __restrict__ seg,
                               int total) {
    int tid = blockIdx.x * blockDim.x + threadIdx.x;
    if (tid >= total) return;
    int b = tid >> 16;          // / HW2
    int p = tid & (HW2 - 1);    // h*256 + w  (source linear index)

    int  emp = g_empty[b];
    bool m   = emp || (seg[tid] > 0.5f);

    float gx = grid[(size_t)b * 2 * HW2 + p];
    float gy = grid[(size_t)b * 2 * HW2 + HW2 + p];
    if (!m) { gx = 0.0f; gy = 0.0f; }

    // grid_int = int32(((g+1)*0.5)*256), trunc toward zero (always >= 0 here), clip
    int ix = (int)((gx + 1.0f) * 0.5f * (float)HW);
    int iy = (int)((gy + 1.0f) * 0.5f * (float)HW);
    ix = min(max(ix, 0), HW - 1);
    iy = min(max(iy, 0), HW - 1);

    atomicMax(&g_scatter[b * HW2 + iy * HW + ix], p);
}

// ---------------------------------------------------------------------------
// K3: decode + nearest sample + write all 5 output channels
//   grid_uv math collapses exactly to: ix = w_src & ~1, iy = h_src & ~1
//   empty cell (-1)  -> round(-0.5) = 0 -> sample (0,0), valid.
// ---------------------------------------------------------------------------
__global__ void gather_kernel(const float* __restrict__ seg,
                              const float* __restrict__ conf,
                              const float* __restrict__ depth,
                              float* __restrict__ out,
                              int bs, int total) {
    int tid = blockIdx.x * blockDim.x + threadIdx.x;
    if (tid >= total) return;
    int b = tid >> 16;
    int p = tid & (HW2 - 1);

    int s = g_scatter[tid];
    int ix = 0, iy = 0;
    if (s >= 0) {
        ix = (s & (HW - 1)) & ~1;   // round-half-even(w - 0.5) == even floor
        iy = (s >> 8) & ~1;
    }

    int src = b * HW2 + iy * HW + ix;
    int emp = __ldg(&g_empty[b]);
    float m = (emp || (__ldg(seg + src) > 0.5f)) ? 1.0f : 0.0f;
    float d = __ldg(depth + src);
    float c = __ldg(conf  + src);

    size_t o0 = (size_t)b * 3 * HW2 + p;
    out[o0]            = ((float)ix / 280.0f) * m;
    out[o0 + HW2]      = ((float)iy / 280.0f) * m;
    out[o0 + 2 * HW2]  = d * m;
    out[(size_t)bs * 3 * HW2 + (size_t)b * HW2 + p] = c;
    out[(size_t)bs * 4 * HW2 + (size_t)b * HW2 + p] = m;
}

// ---------------------------------------------------------------------------
extern "C" void kernel_launch(void* const* d_in, const int* in_sizes, int n_in,
                              void* d_out, int out_size) {
    const float* grid  = (const float*)d_in[0];
    const float* seg   = (const float*)d_in[1];
    const float* conf  = (const float*)d_in[2];
    const float* depth = (const float*)d_in[3];
    float* out = (float*)d_out;

    int bs = in_sizes[1] / HW2;   // 128
    int total = bs * HW2;

    void* sc_ptr = nullptr;
    cudaGetSymbolAddress(&sc_ptr, g_scatter);
    cudaMemsetAsync(sc_ptr, 0xFF, (size_t)total * sizeof(int));  // -1 everywhere

    count_kernel<<<bs, 256>>>(seg);

    int nb = (total + 255) / 256;
    scatter_kernel<<<nb, 256>>>(grid, seg, total);
    gather_kernel<<<nb, 256>>>(seg, conf, depth, out, bs, total);
}

// round 2
// speedup vs baseline: 5.4797x; 5.4797x over previous
#include <cuda_runtime.h>
#include <cuda_bf16.h>
#include <cstdint>

#define HW   256
#define HW2  65536
#define MAX_BS 128

// Scratch (__device__ globals only — no allocations allowed)
__device__ int      g_scatter[MAX_BS * HW2];       // winning in-batch source idx, -1 = empty
__device__ unsigned g_bits[MAX_BS * (HW2 / 32)];   // seg>0.5 bitmask, 1 MB
__device__ int      g_cnt[MAX_BS];                 // # valid per batch
__device__ int      g_mmax[MAX_BS];                // max in-batch p among MASKED pixels, -1 if none

// ---------------------------------------------------------------------------
// K1: build bitmask + per-batch valid count + per-batch max masked index
//     grid = bs*8 blocks, 256 threads; each block covers 8192 pixels
// ---------------------------------------------------------------------------
__global__ void count_kernel(const float* __restrict__ seg) {
    int blk  = blockIdx.x;
    int b    = blk >> 3;
    int sub  = blk & 7;
    int base = b * HW2 + (sub << 13);
    int warp = threadIdx.x >> 5, lane = threadIdx.x & 31;
    int wbase = base + (warp << 10);          // 1024 px per warp

    int cnt = 0, mm = -1;
    #pragma unroll 8
    for (int i = 0; i < 32; i++) {
        int idx = wbase + (i << 5) + lane;
        bool m = seg[idx] > 0.5f;
        unsigned word = __ballot_sync(0xffffffffu, m);
        if (lane == 0) g_bits[idx >> 5] = word;
        cnt += m;
        if (!m) mm = idx - b * HW2;           // ascending loop -> final = max
    }
    #pragma unroll
    for (int o = 16; o; o >>= 1) {
        cnt += __shfl_down_sync(0xffffffffu, cnt, o);
        mm = max(mm, __shfl_down_sync(0xffffffffu, mm, o));
    }
    __shared__ int sc[8], sm[8];
    if (lane == 0) { sc[warp] = cnt; sm[warp] = mm; }
    __syncthreads();
    if (threadIdx.x == 0) {
        int c = 0, m2 = -1;
        #pragma unroll
        for (int i = 0; i < 8; i++) { c += sc[i]; m2 = max(m2, sm[i]); }
        if (c) atomicAdd(&g_cnt[b], c);
        atomicMax(&g_mmax[b], m2);
    }
}

// ---------------------------------------------------------------------------
// K2: scatter (4 px / thread). Masked pixels (non-empty batch) all map to
//     cell (128,128); their winner is precomputed g_mmax -> ONE atomic/batch.
// ---------------------------------------------------------------------------
__global__ void scatter_kernel(const float* __restrict__ grid) {
    int t  = blockIdx.x * blockDim.x + threadIdx.x;
    int p4 = t << 2;                      // global pixel index (multiple of 4)
    int b  = p4 >> 16;
    int p  = p4 & (HW2 - 1);              // in-batch index of first pixel

    bool emp = (__ldg(&g_cnt[b]) == 0);
    unsigned word = __ldg(&g_bits[(b << 11) + (p >> 5)]);

    const float* gbase = grid + (size_t)b * 2 * HW2;
    float4 gx4 = *reinterpret_cast<const float4*>(gbase + p);
    float4 gy4 = *reinterpret_cast<const float4*>(gbase + HW2 + p);
    float gx[4] = {gx4.x, gx4.y, gx4.z, gx4.w};
    float gy[4] = {gy4.x, gy4.y, gy4.z, gy4.w};

    #pragma unroll
    for (int k = 0; k < 4; k++) {
        bool m = emp || ((word >> ((p + k) & 31)) & 1u);
        if (m) {
            int ix = (int)((gx[k] + 1.0f) * 0.5f * (float)HW);
            int iy = (int)((gy[k] + 1.0f) * 0.5f * (float)HW);
            ix = min(max(ix, 0), HW - 1);
            iy = min(max(iy, 0), HW - 1);
            atomicMax(&g_scatter[b * HW2 + iy * HW + ix], p + k);
        }
    }
    // plant the masked-pixel winner once per (non-empty) batch
    if (p == 0 && !emp) {
        int mm = __ldg(&g_mmax[b]);
        if (mm >= 0) atomicMax(&g_scatter[b * HW2 + 128 * HW + 128], mm);
    }
}

// ---------------------------------------------------------------------------
// K3: decode + nearest sample + write all 5 output planes (4 px / thread)
//     ix = w_src & ~1, iy = h_src & ~1 ; empty cell (-1) -> (0,0), valid.
// ---------------------------------------------------------------------------
__global__ void gather_kernel(const float* __restrict__ conf,
                              const float* __restrict__ depth,
                              float* __restrict__ out, int bs) {
    int t  = blockIdx.x * blockDim.x + threadIdx.x;
    int p4 = t << 2;
    int b  = p4 >> 16;
    int p  = p4 & (HW2 - 1);

    bool emp = (__ldg(&g_cnt[b]) == 0);
    int4 s4 = *reinterpret_cast<const int4*>(g_scatter + p4);
    int s[4] = {s4.x, s4.y, s4.z, s4.w};

    float4 ox, oy, od, oc, om;
    float* oxp = &ox.x; float* oyp = &oy.x; float* odp = &od.x;
    float* ocp = &oc.x; float* omp = &om.x;

    const float* db = depth + (size_t)b * HW2;
    const float* cb = conf  + (size_t)b * HW2;
    const unsigned* bb = g_bits + (b << 11);

    #pragma unroll
    for (int k = 0; k < 4; k++) {
        int ix = 0, iy = 0;
        if (s[k] >= 0) {
            ix = (s[k] & (HW - 1)) & ~1;
            iy = (s[k] >> 8) & ~1;
        }
        int cell = iy * HW + ix;
        float m = (emp || ((__ldg(&bb[cell >> 5]) >> (cell & 31)) & 1u)) ? 1.0f : 0.0f;
        float d = __ldg(db + cell);
        float c = __ldg(cb + cell);
        oxp[k] = ((float)ix * (1.0f / 280.0f)) * m;
        oyp[k] = ((float)iy * (1.0f / 280.0f)) * m;
        odp[k] = d * m;
        ocp[k] = c;
        omp[k] = m;
    }

    size_t o0 = (size_t)b * 3 * HW2 + p;
    *reinterpret_cast<float4*>(out + o0)           = ox;
    *reinterpret_cast<float4*>(out + o0 + HW2)     = oy;
    *reinterpret_cast<float4*>(out + o0 + 2 * HW2) = od;
    *reinterpret_cast<float4*>(out + (size_t)bs * 3 * HW2 + (size_t)b * HW2 + p) = oc;
    *reinterpret_cast<float4*>(out + (size_t)bs * 4 * HW2 + (size_t)b * HW2 + p) = om;
}

// ---------------------------------------------------------------------------
extern "C" void kernel_launch(void* const* d_in, const int* in_sizes, int n_in,
                              void* d_out, int out_size) {
    const float* grid  = (const float*)d_in[0];
    const float* seg   = (const float*)d_in[1];
    const float* conf  = (const float*)d_in[2];
    const float* depth = (const float*)d_in[3];
    float* out = (float*)d_out;

    int bs = in_sizes[1] / HW2;       // 128
    int total = bs * HW2;

    void* p_sc = nullptr; cudaGetSymbolAddress(&p_sc, g_scatter);
    void* p_cn = nullptr; cudaGetSymbolAddress(&p_cn, g_cnt);
    void* p_mm = nullptr; cudaGetSymbolAddress(&p_mm, g_mmax);
    cudaMemsetAsync(p_sc, 0xFF, (size_t)total * sizeof(int));
    cudaMemsetAsync(p_cn, 0x00, bs * sizeof(int));
    cudaMemsetAsync(p_mm, 0xFF, bs * sizeof(int));

    count_kernel<<<bs * 8, 256>>>(seg);

    int nthreads = total / 4;
    int nb = (nthreads + 255) / 256;
    scatter_kernel<<<nb, 256>>>(grid);
    gather_kernel<<<nb, 256>>>(conf, depth, out, bs);
}